// round 7
// baseline (speedup 1.0000x reference)
#include <cuda_runtime.h>

#define Bdim 8
#define Ndim 8
#define Tdim 262144
#define ROWS (Bdim * Ndim)            // 64
#define CHUNKS 16                     // chunks per eIF row
#define EIF_BLOCKS (ROWS * CHUNKS)    // 1024
#define RECON_BLOCKS 256
#define GRID (EIF_BLOCKS + RECON_BLOCKS)  // 1280
#define THREADS 256
#define VEC_PER_CHUNK (Tdim / CHUNKS / 4)          // 4096 float4 per chunk
#define EIF_ITERS (VEC_PER_CHUNK / THREADS)        // 16
#define RECON_VEC (Bdim * Tdim / 4)                // 524288 float4 per array
#define RECON_ITERS (RECON_VEC / (RECON_BLOCKS * THREADS))  // 8

// [0]=recon_sum, [1]=if_sum, [2]=smooth_sum. Zero at module load; the
// last-finishing block resets everything after reading, so every
// kernel_launch call (correctness, capture, all replays) starts from zero.
__device__ double g_acc[3];
__device__ unsigned int g_done;

__device__ __forceinline__ float block_reduce(float v, float* sm) {
    #pragma unroll
    for (int o = 16; o > 0; o >>= 1) v += __shfl_down_sync(0xffffffffu, v, o);
    int warp = threadIdx.x >> 5;
    __syncthreads();
    if ((threadIdx.x & 31) == 0) sm[warp] = v;
    __syncthreads();
    if (warp == 0) {
        v = (threadIdx.x < (THREADS >> 5)) ? sm[threadIdx.x] : 0.0f;
        #pragma unroll
        for (int o = 4; o > 0; o >>= 1) v += __shfl_down_sync(0xffffffffu, v, o);
    }
    return v;
}

// Cold path: executed once, by one thread of the last block. Spills are fine.
__device__ __noinline__ void finalize_tail(const int* __restrict__ mode_mask,
                                           float* __restrict__ out) {
    double s_recon  = atomicAdd(&g_acc[0], 0.0);
    double s_if     = atomicAdd(&g_acc[1], 0.0);
    double s_smooth = atomicAdd(&g_acc[2], 0.0);

    float count = 0.0f;
    #pragma unroll
    for (int i = 0; i < ROWS; i++) count += (mode_mask[i] == 1) ? 1.0f : 0.0f;

    const double recon  = s_recon  / ((double)Bdim * (double)Tdim);
    const double ifl    = s_if     / ((double)Bdim * (double)Ndim * (double)Tdim);
    const double smooth = (s_smooth / (double)(Tdim - 1)) / (double)fmaxf(count, 1.0f);
    const double total  = recon + 0.5 * ifl + ((count > 0.0f) ? 0.1 * smooth : 0.0);

    out[0] = (float)total;
    out[1] = (float)recon;
    out[2] = (float)ifl;
    out[3] = (float)smooth;

    // reset ALL device state for the next graph replay
    g_acc[0] = 0.0; g_acc[1] = 0.0; g_acc[2] = 0.0;
    __threadfence();
    g_done = 0u;
}

__global__ void __launch_bounds__(THREADS, 8)   // cap regs at 32 -> 8 blocks/SM
loss_fused_kernel(const float* __restrict__ rr, const float* __restrict__ ri,
                  const float* __restrict__ tr, const float* __restrict__ ti,
                  const float* __restrict__ eIF, const float* __restrict__ tif,
                  const int* __restrict__ mode_mask, float* __restrict__ out)
{
    __shared__ float sm[THREADS / 32];
    const int tid = threadIdx.x;
    const int bid = blockIdx.x;

    if (bid < EIF_BLOCKS) {
        // ---- eIF / target_if path: one (row, chunk) per block ----
        const int row   = bid / CHUNKS;
        const int chunk = bid % CHUNKS;
        if (mode_mask[row] == 1) {       // masked row contributes NOTHING: skip all traffic
            const size_t row_off = (size_t)row * Tdim;
            const float4* __restrict__ e4 = (const float4*)(eIF + row_off);
            const float4* __restrict__ t4 = (const float4*)(tif + row_off);
            const float*  __restrict__ er = eIF + row_off;

            const int vbase = chunk * VEC_PER_CHUNK;
            float acc_if = 0.0f, acc_sm = 0.0f;

            #pragma unroll 4
            for (int i = 0; i < EIF_ITERS; i++) {
                const int v = vbase + i * THREADS + tid;
                const float4 e  = e4[v];
                const float4 tf = t4[v];

                float dx = e.x - tf.x, dy = e.y - tf.y, dz = e.z - tf.z, dw = e.w - tf.w;
                acc_if += dx * dx + dy * dy + dz * dz + dw * dw;

                float d1 = e.y - e.x, d2 = e.z - e.y, d3 = e.w - e.z;
                acc_sm += d1 * d1 + d2 * d2 + d3 * d3;

                // neighbor e[t+4]: next lane's e.x, scalar patch at warp edge
                const int t = v * 4;
                float nx = __shfl_down_sync(0xffffffffu, e.x, 1);
                if ((tid & 31) == 31 && (t + 4 < Tdim)) nx = er[t + 4];
                if (t + 4 < Tdim) { float d4 = nx - e.w; acc_sm += d4 * d4; }
            }

            acc_if = block_reduce(acc_if, sm);
            acc_sm = block_reduce(acc_sm, sm);
            if (tid == 0) {
                atomicAdd(&g_acc[1], (double)acc_if);
                atomicAdd(&g_acc[2], (double)acc_sm);
            }
        }
    } else {
        // ---- recon path: grid-stride over B*T with float4 ----
        const int rb = bid - EIF_BLOCKS;
        const float4* __restrict__ a = (const float4*)rr;
        const float4* __restrict__ b = (const float4*)ri;
        const float4* __restrict__ c = (const float4*)tr;
        const float4* __restrict__ d = (const float4*)ti;

        float acc = 0.0f;
        #pragma unroll
        for (int j = 0; j < RECON_ITERS; j++) {
            const int v = rb * THREADS + tid + j * (RECON_BLOCKS * THREADS);
            const float4 xr = a[v], xt = c[v];
            const float4 yr = b[v], yt = d[v];
            float d0 = xr.x - xt.x, d1 = xr.y - xt.y, d2 = xr.z - xt.z, d3 = xr.w - xt.w;
            acc += d0 * d0 + d1 * d1 + d2 * d2 + d3 * d3;
            float e0 = yr.x - yt.x, e1 = yr.y - yt.y, e2 = yr.z - yt.z, e3 = yr.w - yt.w;
            acc += e0 * e0 + e1 * e1 + e2 * e2 + e3 * e3;
        }
        acc = block_reduce(acc, sm);
        if (tid == 0) atomicAdd(&g_acc[0], (double)acc);
    }

    // ---- completion counter: the last-arriving block finalizes ----
    if (tid == 0) {
        __threadfence();
        unsigned int prev = atomicAdd(&g_done, 1u);
        if (prev == GRID - 1) finalize_tail(mode_mask, out);
    }
}

extern "C" void kernel_launch(void* const* d_in, const int* in_sizes, int n_in,
                              void* d_out, int out_size)
{
    const float* recon_real  = (const float*)d_in[0];
    const float* recon_imag  = (const float*)d_in[1];
    const float* target_real = (const float*)d_in[2];
    const float* target_imag = (const float*)d_in[3];
    const float* eIF         = (const float*)d_in[4];
    const float* target_if   = (const float*)d_in[5];
    const int*   mode_mask   = (const int*)d_in[6];
    float* out = (float*)d_out;

    loss_fused_kernel<<<GRID, THREADS>>>(
        recon_real, recon_imag, target_real, target_imag, eIF, target_if,
        mode_mask, out);
}

// round 9
// speedup vs baseline: 1.2288x; 1.2288x over previous
#include <cuda_runtime.h>

#define Bdim 8
#define Ndim 8
#define Tdim 262144
#define ROWS (Bdim * Ndim)            // 64
#define CHUNKS 16                     // chunks per eIF row
#define EIF_BLOCKS (ROWS * CHUNKS)    // 1024
#define RECON_BLOCKS 256
#define WORK_BLOCKS (EIF_BLOCKS + RECON_BLOCKS)   // 1280
#define GRID (WORK_BLOCKS + 1)        // +1 finalizer block (bid 0)
#define THREADS 256
#define VEC_PER_CHUNK (Tdim / CHUNKS / 4)          // 4096 float4 per chunk
#define EIF_ITERS (VEC_PER_CHUNK / THREADS)        // 16
#define RECON_VEC (Bdim * Tdim / 4)                // 524288 float4 per array
#define RECON_ITERS (RECON_VEC / (RECON_BLOCKS * THREADS))  // 8
#define SLOTS_PER_THREAD (WORK_BLOCKS / THREADS)   // 5

// One 16B slot per working block: {v0, v1, flag, pad}. The 128-bit store is a
// single transaction, so flag+data are published atomically -> no fences.
// Flags zero at module load; the finalizer resets them each run, so every
// kernel_launch call (correctness, capture, all replays) starts clean.
__device__ float4 g_slots[WORK_BLOCKS];

__device__ __forceinline__ void slot_write(int idx, float a, float b) {
    float4* p = &g_slots[idx];
    asm volatile("st.global.v4.f32 [%0], {%1, %2, %3, %4};"
                 :: "l"(p), "f"(a), "f"(b), "f"(1.0f), "f"(0.0f) : "memory");
}

__device__ __forceinline__ float4 slot_read(int idx) {
    float4 v;
    const float4* p = &g_slots[idx];
    asm volatile("ld.volatile.global.v4.f32 {%0, %1, %2, %3}, [%4];"
                 : "=f"(v.x), "=f"(v.y), "=f"(v.z), "=f"(v.w) : "l"(p) : "memory");
    return v;
}

__device__ __forceinline__ float block_reduce(float v, float* sm) {
    #pragma unroll
    for (int o = 16; o > 0; o >>= 1) v += __shfl_down_sync(0xffffffffu, v, o);
    int warp = threadIdx.x >> 5;
    __syncthreads();
    if ((threadIdx.x & 31) == 0) sm[warp] = v;
    __syncthreads();
    if (warp == 0) {
        v = (threadIdx.x < (THREADS >> 5)) ? sm[threadIdx.x] : 0.0f;
        #pragma unroll
        for (int o = 4; o > 0; o >>= 1) v += __shfl_down_sync(0xffffffffu, v, o);
    }
    return v;
}

// Cold path: the dedicated finalizer block. noinline keeps its registers from
// bloating the hot path's allocation.
__device__ __noinline__ void finalize_block(const int* __restrict__ mode_mask,
                                            float* __restrict__ out) {
    const int tid = threadIdx.x;

    // mask count first (one L2/DRAM round trip, overlaps the working grid)
    float count = 0.0f;
    if (tid == 0) {
        int m = 0;
        #pragma unroll
        for (int i = 0; i < ROWS; i++) m += (mode_mask[i] == 1);
        count = (float)m;
    }

    // poll until all WORK_BLOCKS flags are set
    for (;;) {
        int ok = 1;
        #pragma unroll
        for (int j = 0; j < SLOTS_PER_THREAD; j++)
            ok &= (slot_read(j * THREADS + tid).z != 0.0f);
        if (__syncthreads_and(ok)) break;
        __nanosleep(500);
    }

    // deterministic sum of all partials (fixed order, no atomics)
    double rec = 0.0, fif = 0.0, fsm = 0.0;
    #pragma unroll
    for (int j = 0; j < SLOTS_PER_THREAD; j++) {
        const int idx = j * THREADS + tid;
        float4 v = slot_read(idx);
        if (idx < EIF_BLOCKS) { fif += (double)v.x; fsm += (double)v.y; }
        else                  { rec += (double)v.x; }
    }
    __shared__ double sd[3][THREADS / 32];
    #pragma unroll
    for (int o = 16; o > 0; o >>= 1) {
        rec += __shfl_down_sync(0xffffffffu, rec, o);
        fif += __shfl_down_sync(0xffffffffu, fif, o);
        fsm += __shfl_down_sync(0xffffffffu, fsm, o);
    }
    const int warp = tid >> 5;
    if ((tid & 31) == 0) { sd[0][warp] = rec; sd[1][warp] = fif; sd[2][warp] = fsm; }
    __syncthreads();

    if (tid == 0) {
        double R = 0.0, I = 0.0, S = 0.0;
        #pragma unroll
        for (int w = 0; w < THREADS / 32; w++) { R += sd[0][w]; I += sd[1][w]; S += sd[2][w]; }

        const double recon  = R / ((double)Bdim * (double)Tdim);
        const double ifl    = I / ((double)Bdim * (double)Ndim * (double)Tdim);
        const double smooth = (S / (double)(Tdim - 1)) / (double)fmaxf(count, 1.0f);
        const double total  = recon + 0.5 * ifl + ((count > 0.0f) ? 0.1 * smooth : 0.0);

        out[0] = (float)total;
        out[1] = (float)recon;
        out[2] = (float)ifl;
        out[3] = (float)smooth;
    }
    __syncthreads();

    // reset flags for the next graph replay (values get fully rewritten)
    #pragma unroll
    for (int j = 0; j < SLOTS_PER_THREAD; j++) {
        float4* p = &g_slots[j * THREADS + tid];
        asm volatile("st.global.f32 [%0], %1;"
                     :: "l"((char*)p + 8), "f"(0.0f) : "memory");
    }
}

__global__ void __launch_bounds__(THREADS)
loss_fused_kernel(const float* __restrict__ rr, const float* __restrict__ ri,
                  const float* __restrict__ tr, const float* __restrict__ ti,
                  const float* __restrict__ eIF, const float* __restrict__ tif,
                  const int* __restrict__ mode_mask, float* __restrict__ out)
{
    __shared__ float sm[THREADS / 32];
    const int tid = threadIdx.x;
    const int bid = blockIdx.x;

    if (bid == 0) {                    // resident from wave 1; polls slots
        finalize_block(mode_mask, out);
        return;
    }

    const int idx = bid - 1;           // slot index 0..1279

    if (idx < EIF_BLOCKS) {
        // ---- eIF / target_if path: one (row, chunk) per block ----
        const int row   = idx / CHUNKS;
        const int chunk = idx % CHUNKS;
        if (mode_mask[row] != 1) {     // masked row: zero contribution, no traffic
            if (tid == 0) slot_write(idx, 0.0f, 0.0f);
            return;
        }

        const size_t row_off = (size_t)row * Tdim;
        const float4* __restrict__ e4 = (const float4*)(eIF + row_off);
        const float4* __restrict__ t4 = (const float4*)(tif + row_off);
        const float*  __restrict__ er = eIF + row_off;

        const int vbase = chunk * VEC_PER_CHUNK;
        float acc_if = 0.0f, acc_sm = 0.0f;

        #pragma unroll 4
        for (int i = 0; i < EIF_ITERS; i++) {
            const int v = vbase + i * THREADS + tid;
            const float4 e  = e4[v];
            const float4 tf = t4[v];

            float dx = e.x - tf.x, dy = e.y - tf.y, dz = e.z - tf.z, dw = e.w - tf.w;
            acc_if += dx * dx + dy * dy + dz * dz + dw * dw;

            float d1 = e.y - e.x, d2 = e.z - e.y, d3 = e.w - e.z;
            acc_sm += d1 * d1 + d2 * d2 + d3 * d3;

            // neighbor e[t+4]: next lane's e.x, scalar patch at warp edge
            const int t = v * 4;
            float nx = __shfl_down_sync(0xffffffffu, e.x, 1);
            if ((tid & 31) == 31 && (t + 4 < Tdim)) nx = er[t + 4];
            if (t + 4 < Tdim) { float d4 = nx - e.w; acc_sm += d4 * d4; }
        }

        acc_if = block_reduce(acc_if, sm);
        acc_sm = block_reduce(acc_sm, sm);
        if (tid == 0) slot_write(idx, acc_if, acc_sm);   // single STG.128, no fence
    } else {
        // ---- recon path: grid-stride over B*T with float4 ----
        const int rb = idx - EIF_BLOCKS;
        const float4* __restrict__ a = (const float4*)rr;
        const float4* __restrict__ b = (const float4*)ri;
        const float4* __restrict__ c = (const float4*)tr;
        const float4* __restrict__ d = (const float4*)ti;

        float acc = 0.0f;
        #pragma unroll
        for (int j = 0; j < RECON_ITERS; j++) {
            const int v = rb * THREADS + tid + j * (RECON_BLOCKS * THREADS);
            const float4 xr = a[v], xt = c[v];
            const float4 yr = b[v], yt = d[v];
            float d0 = xr.x - xt.x, d1 = xr.y - xt.y, d2 = xr.z - xt.z, d3 = xr.w - xt.w;
            acc += d0 * d0 + d1 * d1 + d2 * d2 + d3 * d3;
            float e0 = yr.x - yt.x, e1 = yr.y - yt.y, e2 = yr.z - yt.z, e3 = yr.w - yt.w;
            acc += e0 * e0 + e1 * e1 + e2 * e2 + e3 * e3;
        }
        acc = block_reduce(acc, sm);
        if (tid == 0) slot_write(idx, acc, 0.0f);        // single STG.128, no fence
    }
}

extern "C" void kernel_launch(void* const* d_in, const int* in_sizes, int n_in,
                              void* d_out, int out_size)
{
    const float* recon_real  = (const float*)d_in[0];
    const float* recon_imag  = (const float*)d_in[1];
    const float* target_real = (const float*)d_in[2];
    const float* target_imag = (const float*)d_in[3];
    const float* eIF         = (const float*)d_in[4];
    const float* target_if   = (const float*)d_in[5];
    const int*   mode_mask   = (const int*)d_in[6];
    float* out = (float*)d_out;

    loss_fused_kernel<<<GRID, THREADS>>>(
        recon_real, recon_imag, target_real, target_imag, eIF, target_if,
        mode_mask, out);
}

// round 10
// speedup vs baseline: 1.3310x; 1.0832x over previous
#include <cuda_runtime.h>

#define Bdim 8
#define Ndim 8
#define Tdim 262144
#define ROWS (Bdim * Ndim)            // 64
#define CHUNKS 32                     // chunks per eIF row (finer granularity)
#define EIF_BLOCKS (ROWS * CHUNKS)    // 2048
#define RECON_BLOCKS 512
#define THREADS 256
#define VEC_PER_CHUNK (Tdim / CHUNKS / 4)          // 2048 float4 per chunk
#define EIF_ITERS (VEC_PER_CHUNK / THREADS)        // 8
#define RECON_VEC (Bdim * Tdim / 4)                // 524288 float4 per array
#define RECON_ITERS (RECON_VEC / (RECON_BLOCKS * THREADS))  // 4

// accumulators: [0]=recon_sum, [1]=if_sum, [2]=smooth_sum (mask-weighted).
// Zero-initialized at module load; finalize_kernel resets them after each
// read so every kernel_launch call (correctness, capture, replays) starts
// from zero.
__device__ double g_acc[3];

__device__ __forceinline__ void pdl_launch_dependents() {
    asm volatile("griddepcontrol.launch_dependents;" ::: "memory");
}
__device__ __forceinline__ void pdl_wait() {
    asm volatile("griddepcontrol.wait;" ::: "memory");
}

__device__ __forceinline__ float block_reduce(float v, float* sm) {
    #pragma unroll
    for (int o = 16; o > 0; o >>= 1) v += __shfl_down_sync(0xffffffffu, v, o);
    int warp = threadIdx.x >> 5;
    __syncthreads();
    if ((threadIdx.x & 31) == 0) sm[warp] = v;
    __syncthreads();
    if (warp == 0) {
        v = (threadIdx.x < (THREADS >> 5)) ? sm[threadIdx.x] : 0.0f;
        #pragma unroll
        for (int o = 4; o > 0; o >>= 1) v += __shfl_down_sync(0xffffffffu, v, o);
    }
    return v;
}

__global__ void __launch_bounds__(THREADS, 6)   // cap ~42 regs -> 6 blocks/SM
loss_main_kernel(const float* __restrict__ rr, const float* __restrict__ ri,
                 const float* __restrict__ tr, const float* __restrict__ ti,
                 const float* __restrict__ eIF, const float* __restrict__ tif,
                 const int* __restrict__ mode_mask)
{
    __shared__ float sm[THREADS / 32];
    const int tid = threadIdx.x;
    const int bid = blockIdx.x;

    // Let the finalize kernel launch early; its griddepcontrol.wait enforces
    // ordering against this grid's memory.
    pdl_launch_dependents();

    if (bid < EIF_BLOCKS) {
        // ---- eIF / target_if path: one (row, chunk) per block, 64 KB ----
        const int row   = bid / CHUNKS;
        const int chunk = bid % CHUNKS;
        if (mode_mask[row] != 1) return;   // masked row contributes NOTHING: skip all traffic

        const size_t row_off = (size_t)row * Tdim;
        const float4* __restrict__ e4 = (const float4*)(eIF + row_off);
        const float4* __restrict__ t4 = (const float4*)(tif + row_off);
        const float*  __restrict__ er = eIF + row_off;

        const int vbase = chunk * VEC_PER_CHUNK;
        float acc_if = 0.0f, acc_sm = 0.0f;

        #pragma unroll 4
        for (int i = 0; i < EIF_ITERS; i++) {
            const int v = vbase + i * THREADS + tid;
            const float4 e  = e4[v];
            const float4 tf = t4[v];

            float dx = e.x - tf.x, dy = e.y - tf.y, dz = e.z - tf.z, dw = e.w - tf.w;
            acc_if += dx * dx + dy * dy + dz * dz + dw * dw;

            float d1 = e.y - e.x, d2 = e.z - e.y, d3 = e.w - e.z;
            acc_sm += d1 * d1 + d2 * d2 + d3 * d3;

            // neighbor element e[t+4]: next lane's e.x, or scalar load at warp edge
            const int t = v * 4;
            float nx = __shfl_down_sync(0xffffffffu, e.x, 1);
            if ((tid & 31) == 31 && (t + 4 < Tdim)) nx = er[t + 4];
            if (t + 4 < Tdim) { float d4 = nx - e.w; acc_sm += d4 * d4; }
        }

        acc_if = block_reduce(acc_if, sm);
        acc_sm = block_reduce(acc_sm, sm);
        if (tid == 0) {
            atomicAdd(&g_acc[1], (double)acc_if);
            atomicAdd(&g_acc[2], (double)acc_sm);
        }
    } else {
        // ---- recon path: contiguous slab per block, 64 KB across 4 arrays ----
        const int rb = bid - EIF_BLOCKS;
        const float4* __restrict__ a = (const float4*)rr;
        const float4* __restrict__ b = (const float4*)ri;
        const float4* __restrict__ c = (const float4*)tr;
        const float4* __restrict__ d = (const float4*)ti;

        float acc = 0.0f;
        #pragma unroll
        for (int j = 0; j < RECON_ITERS; j++) {
            const int v = rb * THREADS + tid + j * (RECON_BLOCKS * THREADS);
            const float4 xr = a[v], xt = c[v];
            const float4 yr = b[v], yt = d[v];
            float d0 = xr.x - xt.x, d1 = xr.y - xt.y, d2 = xr.z - xt.z, d3 = xr.w - xt.w;
            acc += d0 * d0 + d1 * d1 + d2 * d2 + d3 * d3;
            float e0 = yr.x - yt.x, e1 = yr.y - yt.y, e2 = yr.z - yt.z, e3 = yr.w - yt.w;
            acc += e0 * e0 + e1 * e1 + e2 * e2 + e3 * e3;
        }
        acc = block_reduce(acc, sm);
        if (tid == 0) atomicAdd(&g_acc[0], (double)acc);
    }
}

// One warp. PDL: prologue (mask count) overlaps the primary's tail;
// griddepcontrol.wait then orders the g_acc reads after the primary.
__global__ void finalize_kernel(const int* __restrict__ mode_mask, float* __restrict__ out) {
    const int lid = threadIdx.x;   // 0..31

    int m = (mode_mask[lid] == 1) + (mode_mask[lid + 32] == 1);
    #pragma unroll
    for (int o = 16; o > 0; o >>= 1) m += __shfl_down_sync(0xffffffffu, m, o);

    pdl_wait();   // primary grid complete; its atomics to g_acc visible

    if (lid == 0) {
        const float count = (float)m;
        const double s_recon  = g_acc[0];
        const double s_if     = g_acc[1];
        const double s_smooth = g_acc[2];

        const double recon  = s_recon  / ((double)Bdim * (double)Tdim);
        const double ifl    = s_if     / ((double)Bdim * (double)Ndim * (double)Tdim);
        const double smooth = (s_smooth / (double)(Tdim - 1)) / (double)fmaxf(count, 1.0f);
        const double total  = recon + 0.5 * ifl + ((count > 0.0f) ? 0.1 * smooth : 0.0);

        out[0] = (float)total;
        out[1] = (float)recon;
        out[2] = (float)ifl;
        out[3] = (float)smooth;

        // Reset accumulators so the next kernel_launch call starts from zero.
        g_acc[0] = 0.0; g_acc[1] = 0.0; g_acc[2] = 0.0;
    }
}

extern "C" void kernel_launch(void* const* d_in, const int* in_sizes, int n_in,
                              void* d_out, int out_size)
{
    const float* recon_real  = (const float*)d_in[0];
    const float* recon_imag  = (const float*)d_in[1];
    const float* target_real = (const float*)d_in[2];
    const float* target_imag = (const float*)d_in[3];
    const float* eIF         = (const float*)d_in[4];
    const float* target_if   = (const float*)d_in[5];
    const int*   mode_mask   = (const int*)d_in[6];
    float* out = (float*)d_out;

    loss_main_kernel<<<EIF_BLOCKS + RECON_BLOCKS, THREADS>>>(
        recon_real, recon_imag, target_real, target_imag, eIF, target_if, mode_mask);

    cudaLaunchConfig_t cfg = {};
    cfg.gridDim  = dim3(1);
    cfg.blockDim = dim3(32);
    cfg.dynamicSmemBytes = 0;
    cfg.stream = 0;
    cudaLaunchAttribute attr[1];
    attr[0].id = cudaLaunchAttributeProgrammaticStreamSerialization;
    attr[0].val.programmaticStreamSerializationAllowed = 1;
    cfg.attrs = attr;
    cfg.numAttrs = 1;
    cudaLaunchKernelEx(&cfg, finalize_kernel, mode_mask, (float*)d_out);
}

// round 11
// speedup vs baseline: 1.4196x; 1.0665x over previous
#include <cuda_runtime.h>

#define Bdim 8
#define Ndim 8
#define Tdim 262144
#define ROWS (Bdim * Ndim)            // 64
#define CHUNKS 16                     // chunks per eIF row
#define EIF_BLOCKS (ROWS * CHUNKS)    // 1024
#define RECON_BLOCKS 256
#define THREADS 256
#define VEC_PER_CHUNK (Tdim / CHUNKS / 4)          // 4096 float4 per chunk
#define EIF_ITERS (VEC_PER_CHUNK / THREADS)        // 16
#define RECON_VEC (Bdim * Tdim / 4)                // 524288 float4 per array
#define RECON_ITERS (RECON_VEC / (RECON_BLOCKS * THREADS))  // 8

__device__ __forceinline__ void pdl_launch_dependents() {
    asm volatile("griddepcontrol.launch_dependents;" ::: "memory");
}
__device__ __forceinline__ void pdl_wait() {
    asm volatile("griddepcontrol.wait;" ::: "memory");
}

__device__ __forceinline__ float block_reduce(float v, float* sm) {
    #pragma unroll
    for (int o = 16; o > 0; o >>= 1) v += __shfl_down_sync(0xffffffffu, v, o);
    int warp = threadIdx.x >> 5;
    __syncthreads();
    if ((threadIdx.x & 31) == 0) sm[warp] = v;
    __syncthreads();
    if (warp == 0) {
        v = (threadIdx.x < (THREADS >> 5)) ? sm[threadIdx.x] : 0.0f;
        #pragma unroll
        for (int o = 4; o > 0; o >>= 1) v += __shfl_down_sync(0xffffffffu, v, o);
    }
    return v;
}

// Primary: zero the 4 outputs. launch_dependents FIRST so the main kernel
// launches immediately and this kernel's small-kernel floor hides under it.
// The main kernel's pdl_wait (executed just before its out-atomics, >2us in)
// guarantees these stores are visible first.
__global__ void zero_out_kernel(float* __restrict__ out) {
    pdl_launch_dependents();
    if (threadIdx.x < 4) out[threadIdx.x] = 0.0f;
}

__global__ void __launch_bounds__(THREADS)
loss_main_kernel(const float* __restrict__ rr, const float* __restrict__ ri,
                 const float* __restrict__ tr, const float* __restrict__ ti,
                 const float* __restrict__ eIF, const float* __restrict__ tif,
                 const int* __restrict__ mode_mask, float* __restrict__ out)
{
    __shared__ float sm[THREADS / 32];
    __shared__ int cnt2[2];
    const int tid = threadIdx.x;
    const int bid = blockIdx.x;

    if (bid < EIF_BLOCKS) {
        // ---- eIF / target_if path: one (row, chunk) per block ----
        const int row   = bid / CHUNKS;
        const int chunk = bid % CHUNKS;
        if (mode_mask[row] != 1) return;   // masked row: zero contribution, zero traffic

        // mask count (needed for smooth scaling): 2-warp ballot, L2-hot mask
        int mybit = (tid < ROWS) ? (mode_mask[tid] == 1) : 0;
        unsigned bal = __ballot_sync(0xffffffffu, mybit);
        if ((tid >> 5) < 2 && (tid & 31) == 0) cnt2[tid >> 5] = __popc(bal);

        const size_t row_off = (size_t)row * Tdim;
        const float4* __restrict__ e4 = (const float4*)(eIF + row_off);
        const float4* __restrict__ t4 = (const float4*)(tif + row_off);
        const float*  __restrict__ er = eIF + row_off;

        const int vbase = chunk * VEC_PER_CHUNK;
        float acc_if = 0.0f, acc_sm = 0.0f;

        #pragma unroll 4
        for (int i = 0; i < EIF_ITERS; i++) {
            const int v = vbase + i * THREADS + tid;
            const float4 e  = e4[v];
            const float4 tf = t4[v];

            float dx = e.x - tf.x, dy = e.y - tf.y, dz = e.z - tf.z, dw = e.w - tf.w;
            acc_if += dx * dx + dy * dy + dz * dz + dw * dw;

            float d1 = e.y - e.x, d2 = e.z - e.y, d3 = e.w - e.z;
            acc_sm += d1 * d1 + d2 * d2 + d3 * d3;

            // neighbor e[t+4]: next lane's e.x, scalar patch at warp edge
            const int t = v * 4;
            float nx = __shfl_down_sync(0xffffffffu, e.x, 1);
            if ((tid & 31) == 31 && (t + 4 < Tdim)) nx = er[t + 4];
            if (t + 4 < Tdim) { float d4 = nx - e.w; acc_sm += d4 * d4; }
        }

        acc_if = block_reduce(acc_if, sm);   // internal syncthreads publish cnt2 too
        acc_sm = block_reduce(acc_sm, sm);

        if (tid == 0) {
            const float count = (float)(cnt2[0] + cnt2[1]);   // >0 (this row active)
            const float si = acc_if * (1.0f / 16777216.0f);   // / (B*N*T) = 2^-24, exact
            const float ss = acc_sm / (262143.0f * count);    // / ((T-1)*count)
            pdl_wait();    // zero_out_kernel complete; out[] zeroed
            atomicAdd(out + 2, si);
            atomicAdd(out + 3, ss);
            atomicAdd(out + 0, 0.5f * si + 0.1f * ss);
        }
    } else {
        // ---- recon path: grid-stride over B*T with float4 ----
        const int rb = bid - EIF_BLOCKS;
        const float4* __restrict__ a = (const float4*)rr;
        const float4* __restrict__ b = (const float4*)ri;
        const float4* __restrict__ c = (const float4*)tr;
        const float4* __restrict__ d = (const float4*)ti;

        float acc = 0.0f;
        #pragma unroll
        for (int j = 0; j < RECON_ITERS; j++) {
            const int v = rb * THREADS + tid + j * (RECON_BLOCKS * THREADS);
            const float4 xr = a[v], xt = c[v];
            const float4 yr = b[v], yt = d[v];
            float d0 = xr.x - xt.x, d1 = xr.y - xt.y, d2 = xr.z - xt.z, d3 = xr.w - xt.w;
            acc += d0 * d0 + d1 * d1 + d2 * d2 + d3 * d3;
            float e0 = yr.x - yt.x, e1 = yr.y - yt.y, e2 = yr.z - yt.z, e3 = yr.w - yt.w;
            acc += e0 * e0 + e1 * e1 + e2 * e2 + e3 * e3;
        }
        acc = block_reduce(acc, sm);

        if (tid == 0) {
            const float sr = acc * (1.0f / 2097152.0f);       // / (B*T) = 2^-21, exact
            pdl_wait();
            atomicAdd(out + 1, sr);
            atomicAdd(out + 0, sr);
        }
    }
}

extern "C" void kernel_launch(void* const* d_in, const int* in_sizes, int n_in,
                              void* d_out, int out_size)
{
    const float* recon_real  = (const float*)d_in[0];
    const float* recon_imag  = (const float*)d_in[1];
    const float* target_real = (const float*)d_in[2];
    const float* target_imag = (const float*)d_in[3];
    const float* eIF         = (const float*)d_in[4];
    const float* target_if   = (const float*)d_in[5];
    const int*   mode_mask   = (const int*)d_in[6];
    float* out = (float*)d_out;

    // Primary: zero out[]. Its launch_dependents fires at instruction 0.
    zero_out_kernel<<<1, 32>>>(out);

    // Dependent: main kernel, launched with PDL so it starts immediately;
    // ordering vs the zeroing is enforced by pdl_wait before the atomics.
    cudaLaunchConfig_t cfg = {};
    cfg.gridDim  = dim3(EIF_BLOCKS + RECON_BLOCKS);
    cfg.blockDim = dim3(THREADS);
    cfg.dynamicSmemBytes = 0;
    cfg.stream = 0;
    cudaLaunchAttribute attr[1];
    attr[0].id = cudaLaunchAttributeProgrammaticStreamSerialization;
    attr[0].val.programmaticStreamSerializationAllowed = 1;
    cfg.attrs = attr;
    cfg.numAttrs = 1;
    cudaLaunchKernelEx(&cfg, loss_main_kernel,
                       recon_real, recon_imag, target_real, target_imag,
                       eIF, target_if, mode_mask, out);
}

// round 12
// speedup vs baseline: 1.4275x; 1.0056x over previous
#include <cuda_runtime.h>

#define Bdim 8
#define Ndim 8
#define Tdim 262144
#define ROWS (Bdim * Ndim)            // 64
#define CHUNKS 16                     // chunks per eIF row
#define EIF_BLOCKS (ROWS * CHUNKS)    // 1024
#define RECON_BLOCKS 256
#define THREADS 256
#define VEC_PER_CHUNK (Tdim / CHUNKS / 4)          // 4096 float4 per chunk
#define EIF_ITERS (VEC_PER_CHUNK / THREADS)        // 16
#define RECON_VEC (Bdim * Tdim / 4)                // 524288 float4 per array
#define RECON_ITERS (RECON_VEC / (RECON_BLOCKS * THREADS))  // 8

__device__ __forceinline__ void pdl_launch_dependents() {
    asm volatile("griddepcontrol.launch_dependents;" ::: "memory");
}
__device__ __forceinline__ void pdl_wait() {
    asm volatile("griddepcontrol.wait;" ::: "memory");
}

__device__ __forceinline__ float block_reduce(float v, float* sm) {
    #pragma unroll
    for (int o = 16; o > 0; o >>= 1) v += __shfl_down_sync(0xffffffffu, v, o);
    int warp = threadIdx.x >> 5;
    __syncthreads();
    if ((threadIdx.x & 31) == 0) sm[warp] = v;
    __syncthreads();
    if (warp == 0) {
        v = (threadIdx.x < (THREADS >> 5)) ? sm[threadIdx.x] : 0.0f;
        #pragma unroll
        for (int o = 4; o > 0; o >>= 1) v += __shfl_down_sync(0xffffffffu, v, o);
    }
    return v;
}

// Primary: zero the 4 outputs. launch_dependents FIRST so the main kernel
// launches immediately and this kernel's small-kernel floor hides under it.
__global__ void zero_out_kernel(float* __restrict__ out) {
    pdl_launch_dependents();
    if (threadIdx.x < 4) out[threadIdx.x] = 0.0f;
}

__global__ void __launch_bounds__(THREADS, 6)   // cap regs ~42 -> 6 blocks/SM
loss_main_kernel(const float* __restrict__ rr, const float* __restrict__ ri,
                 const float* __restrict__ tr, const float* __restrict__ ti,
                 const float* __restrict__ eIF, const float* __restrict__ tif,
                 const int* __restrict__ mode_mask, float* __restrict__ out)
{
    __shared__ float sm[THREADS / 32];
    __shared__ int cnt2[2];
    const int tid = threadIdx.x;
    const int bid = blockIdx.x;

    if (bid < EIF_BLOCKS) {
        // ---- eIF / target_if path: one (row, chunk) per block ----
        const int row   = bid / CHUNKS;
        const int chunk = bid % CHUNKS;
        if (mode_mask[row] != 1) return;   // masked row: zero contribution, zero traffic

        // mask count (for smooth scaling): 2-warp ballot, L2-hot mask
        int mybit = (tid < ROWS) ? (mode_mask[tid] == 1) : 0;
        unsigned bal = __ballot_sync(0xffffffffu, mybit);
        if ((tid >> 5) < 2 && (tid & 31) == 0) cnt2[tid >> 5] = __popc(bal);

        const size_t row_off = (size_t)row * Tdim;
        const float4* __restrict__ e4 = (const float4*)(eIF + row_off);
        const float4* __restrict__ t4 = (const float4*)(tif + row_off);
        const float*  __restrict__ er = eIF + row_off;

        const int vbase = chunk * VEC_PER_CHUNK;
        float acc_if = 0.0f, acc_sm = 0.0f;

        #pragma unroll 8
        for (int i = 0; i < EIF_ITERS; i++) {
            const int v = vbase + i * THREADS + tid;
            const float4 e  = e4[v];
            const float4 tf = t4[v];

            float dx = e.x - tf.x, dy = e.y - tf.y, dz = e.z - tf.z, dw = e.w - tf.w;
            acc_if += dx * dx + dy * dy + dz * dz + dw * dw;

            float d1 = e.y - e.x, d2 = e.z - e.y, d3 = e.w - e.z;
            acc_sm += d1 * d1 + d2 * d2 + d3 * d3;

            // neighbor e[t+4]: next lane's e.x, scalar patch at warp edge
            const int t = v * 4;
            float nx = __shfl_down_sync(0xffffffffu, e.x, 1);
            if ((tid & 31) == 31 && (t + 4 < Tdim)) nx = er[t + 4];
            if (t + 4 < Tdim) { float d4 = nx - e.w; acc_sm += d4 * d4; }
        }

        acc_if = block_reduce(acc_if, sm);   // internal syncthreads publish cnt2 too
        acc_sm = block_reduce(acc_sm, sm);

        if (tid == 0) {
            const float count = (float)(cnt2[0] + cnt2[1]);   // >0 (this row active)
            const float si = acc_if * (1.0f / 16777216.0f);   // / (B*N*T) = 2^-24, exact
            const float ss = acc_sm / (262143.0f * count);    // / ((T-1)*count)
            pdl_wait();    // zero_out_kernel complete; out[] zeroed
            atomicAdd(out + 2, si);
            atomicAdd(out + 3, ss);
            atomicAdd(out + 0, 0.5f * si + 0.1f * ss);
        }
    } else {
        // ---- recon path: grid-stride over B*T with float4 ----
        const int rb = bid - EIF_BLOCKS;
        const float4* __restrict__ a = (const float4*)rr;
        const float4* __restrict__ b = (const float4*)ri;
        const float4* __restrict__ c = (const float4*)tr;
        const float4* __restrict__ d = (const float4*)ti;

        float acc = 0.0f;
        #pragma unroll
        for (int j = 0; j < RECON_ITERS; j++) {
            const int v = rb * THREADS + tid + j * (RECON_BLOCKS * THREADS);
            const float4 xr = a[v], xt = c[v];
            const float4 yr = b[v], yt = d[v];
            float d0 = xr.x - xt.x, d1 = xr.y - xt.y, d2 = xr.z - xt.z, d3 = xr.w - xt.w;
            acc += d0 * d0 + d1 * d1 + d2 * d2 + d3 * d3;
            float e0 = yr.x - yt.x, e1 = yr.y - yt.y, e2 = yr.z - yt.z, e3 = yr.w - yt.w;
            acc += e0 * e0 + e1 * e1 + e2 * e2 + e3 * e3;
        }
        acc = block_reduce(acc, sm);

        if (tid == 0) {
            const float sr = acc * (1.0f / 2097152.0f);       // / (B*T) = 2^-21, exact
            pdl_wait();
            atomicAdd(out + 1, sr);
            atomicAdd(out + 0, sr);
        }
    }
}

extern "C" void kernel_launch(void* const* d_in, const int* in_sizes, int n_in,
                              void* d_out, int out_size)
{
    const float* recon_real  = (const float*)d_in[0];
    const float* recon_imag  = (const float*)d_in[1];
    const float* target_real = (const float*)d_in[2];
    const float* target_imag = (const float*)d_in[3];
    const float* eIF         = (const float*)d_in[4];
    const float* target_if   = (const float*)d_in[5];
    const int*   mode_mask   = (const int*)d_in[6];
    float* out = (float*)d_out;

    // Primary: zero out[]. Its launch_dependents fires at instruction 0.
    zero_out_kernel<<<1, 32>>>(out);

    // Dependent: main kernel, launched with PDL so it starts immediately;
    // ordering vs the zeroing is enforced by pdl_wait before the atomics.
    cudaLaunchConfig_t cfg = {};
    cfg.gridDim  = dim3(EIF_BLOCKS + RECON_BLOCKS);
    cfg.blockDim = dim3(THREADS);
    cfg.dynamicSmemBytes = 0;
    cfg.stream = 0;
    cudaLaunchAttribute attr[1];
    attr[0].id = cudaLaunchAttributeProgrammaticStreamSerialization;
    attr[0].val.programmaticStreamSerializationAllowed = 1;
    cfg.attrs = attr;
    cfg.numAttrs = 1;
    cudaLaunchKernelEx(&cfg, loss_main_kernel,
                       recon_real, recon_imag, target_real, target_imag,
                       eIF, target_if, mode_mask, out);
}